// round 4
// baseline (speedup 1.0000x reference)
#include <cuda_runtime.h>
#include <math.h>

// ---------------------------------------------------------------------------
// Problem constants
// ---------------------------------------------------------------------------
#define TT   1024
#define BB   128
#define HH   256
#define EE   58
#define OUTD 33
#define BH   (BB*HH)                 // 32768
#define HN_OFF (TT*BB*OUTD)          // 4325376
#define CN_OFF (HN_OFF + 2*BH)       // 4390912

// Decomposition: 4 batch groups (32 rows) x 32 hidden groups (8 units) = 128 CTAs
#define GBN 4
#define MB  32
#define WS  36        // smem stride for weight tiles [K][32] (padded)
#define GS  36        // gates tile stride
#define AS  512       // A staging stride (row-major [m][k])

// Shared memory layout (float offsets)
#define OFF_WIH0 0            // [64][36]  = 2304
#define OFF_WHH0 2304         // [256][36] = 9216
#define OFF_WIH1 11520        // [256][36]
#define OFF_WHH1 20736        // [256][36]
#define OFF_X    29952        // [32][64]  = 2048
#define OFF_A    32000        // [32][512] = 16384
#define OFF_G    48384        // [32][36]  = 1152
#define OFF_B0   49536        // [32]
#define OFF_B1   49568        // [32]
#define SMEM_FLOATS 49600
#define SMEM_BYTES  (SMEM_FLOATS*4)   // 198400

#define PS 260                // projection smem stride
#define PROJ_SMEM ((33*PS + 32*PS + 64)*4)

// ---------------------------------------------------------------------------
// Global scratch (static __device__ arrays: allocation-free)
// ---------------------------------------------------------------------------
__device__ __align__(16) float g_h0[2][BH];   // layer0 h, double-buffered
__device__ __align__(16) float g_h1[2][BH];   // layer1 h, double-buffered
__device__ __align__(16) float g_y1[(size_t)TT * BH];  // layer1 outputs (128 MB)
__device__ unsigned g_bar[2][GBN];            // spin-barrier counters

// ---------------------------------------------------------------------------
// Reset kernel: runs first each replay. Copies initial h into buffer 0 and
// zeroes the barrier counters (deterministic across graph replays).
// ---------------------------------------------------------------------------
__global__ void reset_kernel(const float* __restrict__ h0in) {
    int i = blockIdx.x * blockDim.x + threadIdx.x;
    if (i < BH) {
        g_h0[0][i] = h0in[i];
        g_h1[0][i] = h0in[BH + i];
    }
    if (i < 2*GBN) ((unsigned*)g_bar)[i] = 0u;
}

// ---------------------------------------------------------------------------
// GEMM micro-tile: acc[2][4] += A[2 rows][k] * W[k][4 cols]
// A is row-major [m][k] (phase-broadcast LDS -> conflict-free),
// W is [k][32] with stride WS, cols tx*4 (contiguous 16B per phase).
// ---------------------------------------------------------------------------
template<int K, int ASTRIDE>
__device__ __forceinline__ void gemm_acc(const float* __restrict__ Abase,
                                         const float* __restrict__ Wbase,
                                         float acc[2][4])
{
#pragma unroll 4
    for (int k = 0; k < K; k += 4) {
        float4 a0 = *reinterpret_cast<const float4*>(Abase + k);
        float4 a1 = *reinterpret_cast<const float4*>(Abase + ASTRIDE + k);
        float4 w0 = *reinterpret_cast<const float4*>(Wbase + (k+0)*WS);
        float4 w1 = *reinterpret_cast<const float4*>(Wbase + (k+1)*WS);
        float4 w2 = *reinterpret_cast<const float4*>(Wbase + (k+2)*WS);
        float4 w3 = *reinterpret_cast<const float4*>(Wbase + (k+3)*WS);

        acc[0][0] += a0.x*w0.x; acc[0][1] += a0.x*w0.y; acc[0][2] += a0.x*w0.z; acc[0][3] += a0.x*w0.w;
        acc[1][0] += a1.x*w0.x; acc[1][1] += a1.x*w0.y; acc[1][2] += a1.x*w0.z; acc[1][3] += a1.x*w0.w;

        acc[0][0] += a0.y*w1.x; acc[0][1] += a0.y*w1.y; acc[0][2] += a0.y*w1.z; acc[0][3] += a0.y*w1.w;
        acc[1][0] += a1.y*w1.x; acc[1][1] += a1.y*w1.y; acc[1][2] += a1.y*w1.z; acc[1][3] += a1.y*w1.w;

        acc[0][0] += a0.z*w2.x; acc[0][1] += a0.z*w2.y; acc[0][2] += a0.z*w2.z; acc[0][3] += a0.z*w2.w;
        acc[1][0] += a1.z*w2.x; acc[1][1] += a1.z*w2.y; acc[1][2] += a1.z*w2.z; acc[1][3] += a1.z*w2.w;

        acc[0][0] += a0.w*w3.x; acc[0][1] += a0.w*w3.y; acc[0][2] += a0.w*w3.z; acc[0][3] += a0.w*w3.w;
        acc[1][0] += a1.w*w3.x; acc[1][1] += a1.w*w3.y; acc[1][2] += a1.w*w3.z; acc[1][3] += a1.w*w3.w;
    }
}

__device__ __forceinline__ float sigmoidf_(float x) {
    return 1.0f / (1.0f + expf(-x));
}

// Batch-group spin barrier (monotonic counter; 32 CTAs per group, all resident)
__device__ __forceinline__ void group_barrier(int which, int gb, unsigned target) {
    __threadfence();
    __syncthreads();
    if (threadIdx.x == 0) {
        atomicAdd(&g_bar[which][gb], 1u);
        while (*((volatile unsigned*)&g_bar[which][gb]) < target) { }
        __threadfence();
    }
    __syncthreads();
}

// ---------------------------------------------------------------------------
// Persistent 2-layer LSTM kernel: grid 128 CTAs x 128 threads
// ---------------------------------------------------------------------------
__global__ __launch_bounds__(128, 1)
void lstm_persistent(const float* __restrict__ x,
                     const float* __restrict__ c0in,
                     const float* __restrict__ Wih0, const float* __restrict__ Whh0,
                     const float* __restrict__ bih0, const float* __restrict__ bhh0,
                     const float* __restrict__ Wih1, const float* __restrict__ Whh1,
                     const float* __restrict__ bih1, const float* __restrict__ bhh1,
                     float* __restrict__ out)
{
    extern __shared__ float sm[];
    float* WIH0s = sm + OFF_WIH0;
    float* WHH0s = sm + OFF_WHH0;
    float* WIH1s = sm + OFF_WIH1;
    float* WHH1s = sm + OFF_WHH1;
    float* Xs    = sm + OFF_X;
    float* Asm   = sm + OFF_A;
    float* Gs    = sm + OFF_G;
    float* B0s   = sm + OFF_B0;
    float* B1s   = sm + OFF_B1;

    const int tid = threadIdx.x;
    const int gb  = blockIdx.x >> 5;   // batch group 0..3
    const int gn  = blockIdx.x & 31;   // hidden group 0..31
    const int b0  = gb * MB;

    // ---- stage weights (once) ----
    for (int idx = tid; idx < 32*64; idx += 128) {
        int j = idx >> 6, k = idx & 63;
        int gc = ((j >> 3) << 8) + (gn << 3) + (j & 7);
        WIH0s[k*WS + j] = (k < EE) ? Wih0[gc*EE + k] : 0.0f;
    }
    for (int idx = tid; idx < 32*256; idx += 128) {
        int j = idx >> 8, k = idx & 255;
        int gc = ((j >> 3) << 8) + (gn << 3) + (j & 7);
        WHH0s[k*WS + j] = Whh0[gc*HH + k];
        WIH1s[k*WS + j] = Wih1[gc*HH + k];
        WHH1s[k*WS + j] = Whh1[gc*HH + k];
    }
    if (tid < 32) {
        int gc = ((tid >> 3) << 8) + (gn << 3) + (tid & 7);
        B0s[tid] = bih0[gc] + bhh0[gc];
        B1s[tid] = bih1[gc] + bhh1[gc];
    }

    // per-thread elementwise mapping: (batch eb, hidden q0 and q0+4)
    const int eb = tid & 31, q0 = tid >> 5;
    const int hg0 = (gn << 3) + q0, hg1 = hg0 + 4;
    const int bg  = b0 + eb;
    float c0r[2], c1r[2], hl0[2], hl1[2];
    c0r[0] = c0in[bg*HH + hg0];       c0r[1] = c0in[bg*HH + hg1];
    c1r[0] = c0in[BH + bg*HH + hg0];  c1r[1] = c0in[BH + bg*HH + hg1];
    hl0[0] = hl0[1] = hl1[0] = hl1[1] = 0.0f;

    // GEMM thread mapping
    const int tx = tid & 7, ty = tid >> 3;
    const float* Arow = Asm + (ty*2)*AS;
    const float* Xrow = Xs  + (ty*2)*64;

    __syncthreads();

    for (int t = 0; t < TT; ++t) {
        const int rp = t & 1, wp = rp ^ 1;

        // ---- stage x[t] and h0[t-1] ----
        for (int idx = tid; idx < MB*64; idx += 128) {
            int m = idx >> 6, e = idx & 63;
            Xs[idx] = (e < EE) ? x[(size_t)t*BB*EE + (size_t)(b0+m)*EE + e] : 0.0f;
        }
        {
            const float4* src = reinterpret_cast<const float4*>(&g_h0[rp][b0*HH]);
            for (int idx = tid; idx < MB*64; idx += 128) {
                int m = idx >> 6, c = idx & 63;
                float4 v = __ldcg(src + m*64 + c);
                *reinterpret_cast<float4*>(&Asm[m*AS + c*4]) = v;
            }
        }
        __syncthreads();

        // ---- layer 0 GEMM: gates = x@Wih0^T + h@Whh0^T + b ----
        {
            float acc[2][4] = {{0,0,0,0},{0,0,0,0}};
            gemm_acc<64, 64>(Xrow, WIH0s + tx*4, acc);
            gemm_acc<256, AS>(Arow, WHH0s + tx*4, acc);
#pragma unroll
            for (int mi = 0; mi < 2; ++mi) {
#pragma unroll
                for (int ni = 0; ni < 4; ++ni) acc[mi][ni] += B0s[tx*4 + ni];
                *reinterpret_cast<float4*>(&Gs[(ty*2+mi)*GS + tx*4]) =
                    make_float4(acc[mi][0], acc[mi][1], acc[mi][2], acc[mi][3]);
            }
        }
        __syncthreads();

        // ---- layer 0 elementwise ----
#pragma unroll
        for (int z = 0; z < 2; ++z) {
            int q = q0 + 4*z;
            float gi = Gs[eb*GS + q];
            float gf = Gs[eb*GS + 8 + q];
            float gg = Gs[eb*GS + 16 + q];
            float go = Gs[eb*GS + 24 + q];
            float iv = sigmoidf_(gi), fv = sigmoidf_(gf);
            float gv = tanhf(gg),     ov = sigmoidf_(go);
            c0r[z] = fv * c0r[z] + iv * gv;
            float hv = ov * tanhf(c0r[z]);
            hl0[z] = hv;
            __stcg(&g_h0[wp][bg*HH + (z ? hg1 : hg0)], hv);
        }
        group_barrier(0, gb, 32u*(t+1));

        // ---- stage y0 (fresh h0) and h1[t-1] ----
        {
            const float4* s0 = reinterpret_cast<const float4*>(&g_h0[wp][b0*HH]);
            const float4* s1 = reinterpret_cast<const float4*>(&g_h1[rp][b0*HH]);
            for (int idx = tid; idx < MB*64; idx += 128) {
                int m = idx >> 6, c = idx & 63;
                float4 v0 = __ldcg(s0 + m*64 + c);
                float4 v1 = __ldcg(s1 + m*64 + c);
                *reinterpret_cast<float4*>(&Asm[m*AS + c*4])       = v0;
                *reinterpret_cast<float4*>(&Asm[m*AS + 256 + c*4]) = v1;
            }
        }
        __syncthreads();

        // ---- layer 1 GEMM: gates = y0@Wih1^T + h1@Whh1^T + b ----
        {
            float acc[2][4] = {{0,0,0,0},{0,0,0,0}};
            gemm_acc<256, AS>(Arow,       WIH1s + tx*4, acc);
            gemm_acc<256, AS>(Arow + 256, WHH1s + tx*4, acc);
#pragma unroll
            for (int mi = 0; mi < 2; ++mi) {
#pragma unroll
                for (int ni = 0; ni < 4; ++ni) acc[mi][ni] += B1s[tx*4 + ni];
                *reinterpret_cast<float4*>(&Gs[(ty*2+mi)*GS + tx*4]) =
                    make_float4(acc[mi][0], acc[mi][1], acc[mi][2], acc[mi][3]);
            }
        }
        __syncthreads();

        // ---- layer 1 elementwise (+ y1 store for projection) ----
#pragma unroll
        for (int z = 0; z < 2; ++z) {
            int q = q0 + 4*z;
            float gi = Gs[eb*GS + q];
            float gf = Gs[eb*GS + 8 + q];
            float gg = Gs[eb*GS + 16 + q];
            float go = Gs[eb*GS + 24 + q];
            float iv = sigmoidf_(gi), fv = sigmoidf_(gf);
            float gv = tanhf(gg),     ov = sigmoidf_(go);
            c1r[z] = fv * c1r[z] + iv * gv;
            float hv = ov * tanhf(c1r[z]);
            hl1[z] = hv;
            int hg = z ? hg1 : hg0;
            __stcg(&g_h1[wp][bg*HH + hg], hv);
            g_y1[(size_t)t*BH + (size_t)bg*HH + hg] = hv;
        }
        group_barrier(1, gb, 32u*(t+1));
    }

    // ---- final hn / cn ----
#pragma unroll
    for (int z = 0; z < 2; ++z) {
        int hg = z ? hg1 : hg0;
        out[HN_OFF +      bg*HH + hg] = hl0[z];
        out[HN_OFF + BH + bg*HH + hg] = hl1[z];
        out[CN_OFF +      bg*HH + hg] = c0r[z];
        out[CN_OFF + BH + bg*HH + hg] = c1r[z];
    }
}

// ---------------------------------------------------------------------------
// Output projection: out = softplus(y1 @ W_out^T + b_out)
// grid = 4096 (t x 4 batch groups), 128 threads
// ---------------------------------------------------------------------------
__global__ __launch_bounds__(128)
void proj_kernel(const float* __restrict__ Wout,
                 const float* __restrict__ bout,
                 float* __restrict__ out)
{
    extern __shared__ float sm[];
    float* ws = sm;                  // [33][PS]
    float* ys = sm + 33*PS;          // [32][PS]
    float* bs = sm + 33*PS + 32*PS;  // [33]

    const int tid = threadIdx.x;
    const int t  = blockIdx.x >> 2;
    const int b0 = (blockIdx.x & 3) * 32;

    for (int idx = tid; idx < 33*256; idx += 128) {
        int o = idx >> 8, k = idx & 255;
        ws[o*PS + k] = Wout[idx];
    }
    if (tid < 33) bs[tid] = bout[tid];
    {
        const float* ysrc = &g_y1[(size_t)t*BH + (size_t)b0*HH];
        for (int idx = tid; idx < 32*256; idx += 128) {
            int m = idx >> 8, k = idx & 255;
            ys[m*PS + k] = ysrc[idx];
        }
    }
    __syncthreads();

    for (int oidx = tid; oidx < 33*32; oidx += 128) {
        int o = oidx >> 5, m = oidx & 31;
        const float* yp = &ys[m*PS];
        const float* wp = &ws[o*PS];
        float s = bs[o];
#pragma unroll 8
        for (int k = 0; k < 256; k += 4) {
            float4 y4 = *reinterpret_cast<const float4*>(yp + k);
            float4 w4 = *reinterpret_cast<const float4*>(wp + k);
            s += y4.x*w4.x + y4.y*w4.y + y4.z*w4.z + y4.w*w4.w;
        }
        // numerically stable softplus
        float sp = fmaxf(s, 0.0f) + log1pf(expf(-fabsf(s)));
        out[(size_t)t*BB*OUTD + (size_t)(b0+m)*OUTD + o] = sp;
    }
}

// ---------------------------------------------------------------------------
// kernel_launch
// ---------------------------------------------------------------------------
extern "C" void kernel_launch(void* const* d_in, const int* in_sizes, int n_in,
                              void* d_out, int out_size) {
    (void)in_sizes; (void)n_in; (void)out_size;
    const float* x    = (const float*)d_in[0];
    const float* h0   = (const float*)d_in[1];
    const float* c0   = (const float*)d_in[2];
    const float* Wih0 = (const float*)d_in[3];
    const float* Whh0 = (const float*)d_in[4];
    const float* bih0 = (const float*)d_in[5];
    const float* bhh0 = (const float*)d_in[6];
    const float* Wih1 = (const float*)d_in[7];
    const float* Whh1 = (const float*)d_in[8];
    const float* bih1 = (const float*)d_in[9];
    const float* bhh1 = (const float*)d_in[10];
    const float* Wout = (const float*)d_in[11];
    const float* bout = (const float*)d_in[12];
    float* out = (float*)d_out;

    cudaFuncSetAttribute(lstm_persistent,
                         cudaFuncAttributeMaxDynamicSharedMemorySize, SMEM_BYTES);
    cudaFuncSetAttribute(proj_kernel,
                         cudaFuncAttributeMaxDynamicSharedMemorySize, PROJ_SMEM);

    reset_kernel<<<128, 256>>>(h0);
    lstm_persistent<<<128, 128, SMEM_BYTES>>>(
        x, c0, Wih0, Whh0, bih0, bhh0, Wih1, Whh1, bih1, bhh1, out);
    proj_kernel<<<4096, 128, PROJ_SMEM>>>(Wout, bout, out);
}